// round 2
// baseline (speedup 1.0000x reference)
#include <cuda_runtime.h>
#include <math.h>

#define ND   1024
#define NH   16
#define HD   64
#define SEQ  2048
#define BATCH 4
#define MTOT (BATCH*SEQ)   // 8192

// Scratch (device globals: allocation-free per harness rules)
__device__ float g_Q [(size_t)MTOT*ND];
__device__ float g_K [(size_t)MTOT*ND];
__device__ float g_V [(size_t)MTOT*ND];
__device__ float g_Ao[(size_t)MTOT*ND];

// ---------------------------------------------------------------------------
// C[M,N] = A[M,K] @ B[N,K]^T + bias[N]
// 64x64 tile, BK=16, 256 threads, 4x4 micro-tile
// ---------------------------------------------------------------------------
__global__ __launch_bounds__(256) void gemm_bias(
    const float* __restrict__ A, const float* __restrict__ B,
    const float* __restrict__ bias, float* __restrict__ C,
    int M, int N, int K)
{
    __shared__ float As[16][64];
    __shared__ float Bs[16][64];
    const int tid = threadIdx.x;
    const int tx = tid & 15, ty = tid >> 4;
    const int m0 = blockIdx.y << 6;
    const int n0 = blockIdx.x << 6;
    const int lRow = tid >> 2;          // 0..63
    const int lCol = (tid & 3) << 2;    // 0,4,8,12

    const float* Ap = A + (size_t)(m0 + lRow) * K + lCol;
    const float* Bp = B + (size_t)(n0 + lRow) * K + lCol;

    float acc[4][4] = {};
    for (int k0 = 0; k0 < K; k0 += 16) {
        float4 av = *(const float4*)(Ap + k0);
        float4 bv = *(const float4*)(Bp + k0);
        As[lCol+0][lRow]=av.x; As[lCol+1][lRow]=av.y;
        As[lCol+2][lRow]=av.z; As[lCol+3][lRow]=av.w;
        Bs[lCol+0][lRow]=bv.x; Bs[lCol+1][lRow]=bv.y;
        Bs[lCol+2][lRow]=bv.z; Bs[lCol+3][lRow]=bv.w;
        __syncthreads();
        #pragma unroll
        for (int kk = 0; kk < 16; kk++) {
            float a[4], b[4];
            *(float4*)a = *(const float4*)&As[kk][ty<<2];
            *(float4*)b = *(const float4*)&Bs[kk][tx<<2];
            #pragma unroll
            for (int i = 0; i < 4; i++)
                #pragma unroll
                for (int j = 0; j < 4; j++)
                    acc[i][j] += a[i] * b[j];
        }
        __syncthreads();
    }
    #pragma unroll
    for (int i = 0; i < 4; i++) {
        const int row = m0 + (ty<<2) + i;
        const int col = n0 + (tx<<2);
        float4 o;
        o.x = acc[i][0] + bias[col+0];
        o.y = acc[i][1] + bias[col+1];
        o.z = acc[i][2] + bias[col+2];
        o.w = acc[i][3] + bias[col+3];
        *(float4*)(C + (size_t)row * N + col) = o;
    }
}

// ---------------------------------------------------------------------------
// Flash-style attention: one block = (head, batch, 64-query tile)
// Q/K/V layout: [b, t, h*64+d] (projection output as-is)
// No 1/sqrt(d) scaling (matches reference!)
// ---------------------------------------------------------------------------
#define SQ_STRIDE 68   // padded to avoid bank conflicts

__global__ __launch_bounds__(256) void attn_kernel(
    const float* __restrict__ Q, const float* __restrict__ K,
    const float* __restrict__ V, float* __restrict__ O)
{
    extern __shared__ float smem[];
    float* sQ     = smem;                   // 64 x 68  (q-major)
    float* sKt    = sQ  + 64*SQ_STRIDE;     // 64 x 64  (d-major: sKt[d*64+k])
    float* sV     = sKt + 64*64;            // 64 x 68  (k-major)
    float* sS     = sV  + 64*SQ_STRIDE;     // 64 x 68
    float* sM     = sS  + 64*SQ_STRIDE;     // 64
    float* sL     = sM  + 64;               // 64
    float* sScale = sL  + 64;               // 64

    const int tid = threadIdx.x;
    const int tx = tid & 15, ty = tid >> 4;
    const int hb = blockIdx.x;              // 0..63
    const int b  = hb & 3, h = hb >> 2;
    const int q0 = blockIdx.y << 6;
    const size_t base = (size_t)b * SEQ * ND + h * HD;

    // Load Q tile (rows q0..q0+63, 64 dims)
    {
        const int r = tid >> 2;             // 0..63
        const int c = (tid & 3) << 2;       // 0,4,8,12
        #pragma unroll
        for (int cc = 0; cc < 4; cc++) {
            const int d = cc*16 + c;
            float4 v = *(const float4*)(Q + base + (size_t)(q0 + r)*ND + d);
            *(float4*)&sQ[r*SQ_STRIDE + d] = v;
        }
    }
    if (tid < 64) { sM[tid] = -1e30f; sL[tid] = 0.f; }
    float accO[4][4] = {};
    __syncthreads();

    for (int k0 = 0; k0 < SEQ; k0 += 64) {
        // Load K (transposed -> d-major) and V (natural, padded)
        {
            const int r = tid >> 2;
            const int c = (tid & 3) << 2;
            #pragma unroll
            for (int cc = 0; cc < 4; cc++) {
                const int d = cc*16 + c;
                float4 kv = *(const float4*)(K + base + (size_t)(k0 + r)*ND + d);
                sKt[(d+0)*64 + r] = kv.x;
                sKt[(d+1)*64 + r] = kv.y;
                sKt[(d+2)*64 + r] = kv.z;
                sKt[(d+3)*64 + r] = kv.w;
                float4 vv = *(const float4*)(V + base + (size_t)(k0 + r)*ND + d);
                *(float4*)&sV[r*SQ_STRIDE + d] = vv;
            }
        }
        __syncthreads();

        // S = Q @ K^T    (rows ty*4+i, cols tx*4+j)
        float s[4][4] = {};
        #pragma unroll
        for (int dd = 0; dd < 64; dd++) {
            float a[4], bb[4];
            #pragma unroll
            for (int i = 0; i < 4; i++) a[i] = sQ[(ty*4+i)*SQ_STRIDE + dd];
            *(float4*)bb = *(const float4*)&sKt[dd*64 + (tx<<2)];
            #pragma unroll
            for (int i = 0; i < 4; i++)
                #pragma unroll
                for (int j = 0; j < 4; j++)
                    s[i][j] += a[i] * bb[j];
        }
        #pragma unroll
        for (int i = 0; i < 4; i++)
            *(float4*)&sS[(ty*4+i)*SQ_STRIDE + (tx<<2)] =
                make_float4(s[i][0], s[i][1], s[i][2], s[i][3]);
        __syncthreads();

        // Online softmax: 4 threads per row, quad shfl reduction
        {
            const int row = tid >> 2, seg = tid & 3;
            float mx = -1e30f;
            #pragma unroll
            for (int c2 = 0; c2 < 16; c2++)
                mx = fmaxf(mx, sS[row*SQ_STRIDE + seg*16 + c2]);
            mx = fmaxf(mx, __shfl_xor_sync(0xffffffffu, mx, 1));
            mx = fmaxf(mx, __shfl_xor_sync(0xffffffffu, mx, 2));
            const float mold = sM[row];
            const float mnew = fmaxf(mold, mx);
            float sum = 0.f;
            #pragma unroll
            for (int c2 = 0; c2 < 16; c2++) {
                float p = __expf(sS[row*SQ_STRIDE + seg*16 + c2] - mnew);
                sS[row*SQ_STRIDE + seg*16 + c2] = p;
                sum += p;
            }
            sum += __shfl_xor_sync(0xffffffffu, sum, 1);
            sum += __shfl_xor_sync(0xffffffffu, sum, 2);
            if (seg == 0) {
                const float sc = __expf(mold - mnew);
                sScale[row] = sc;
                sM[row] = mnew;
                sL[row] = sL[row] * sc + sum;
            }
        }
        __syncthreads();

        // Rescale accumulators, then O += P @ V
        #pragma unroll
        for (int i = 0; i < 4; i++) {
            const float sc = sScale[ty*4+i];
            #pragma unroll
            for (int j = 0; j < 4; j++) accO[i][j] *= sc;
        }
        #pragma unroll
        for (int kk = 0; kk < 64; kk++) {
            float p[4], vv[4];
            #pragma unroll
            for (int i = 0; i < 4; i++) p[i] = sS[(ty*4+i)*SQ_STRIDE + kk];
            *(float4*)vv = *(const float4*)&sV[kk*SQ_STRIDE + (tx<<2)];
            #pragma unroll
            for (int i = 0; i < 4; i++)
                #pragma unroll
                for (int j = 0; j < 4; j++)
                    accO[i][j] += p[i] * vv[j];
        }
        __syncthreads();
    }

    // Normalize by l and write out (same [b,t,h*64+d] layout)
    #pragma unroll
    for (int i = 0; i < 4; i++) {
        const int q = q0 + ty*4 + i;
        const float inv = 1.0f / sL[ty*4+i];
        float4 o = make_float4(accO[i][0]*inv, accO[i][1]*inv,
                               accO[i][2]*inv, accO[i][3]*inv);
        *(float4*)(O + base + (size_t)q*ND + (tx<<2)) = o;
    }
}

// ---------------------------------------------------------------------------
extern "C" void kernel_launch(void* const* d_in, const int* in_sizes, int n_in,
                              void* d_out, int out_size)
{
    const float* x  = (const float*)d_in[0];
    const float* Wq = (const float*)d_in[1];
    const float* bq = (const float*)d_in[2];
    const float* Wk = (const float*)d_in[3];
    const float* bk = (const float*)d_in[4];
    const float* Wv = (const float*)d_in[5];
    const float* bv = (const float*)d_in[6];
    const float* Wp = (const float*)d_in[7];
    const float* bp = (const float*)d_in[8];
    float* out = (float*)d_out;

    float *Qp, *Kp, *Vp, *Op;
    cudaGetSymbolAddress((void**)&Qp, g_Q);
    cudaGetSymbolAddress((void**)&Kp, g_K);
    cudaGetSymbolAddress((void**)&Vp, g_V);
    cudaGetSymbolAddress((void**)&Op, g_Ao);

    const dim3 gg(ND/64, MTOT/64);   // (16, 128)
    gemm_bias<<<gg, 256>>>(x, Wq, bq, Qp, MTOT, ND, ND);
    gemm_bias<<<gg, 256>>>(x, Wk, bk, Kp, MTOT, ND, ND);
    gemm_bias<<<gg, 256>>>(x, Wv, bv, Vp, MTOT, ND, ND);

    const size_t smem_bytes =
        (size_t)(64*SQ_STRIDE*3 + 64*64 + 3*64) * sizeof(float);  // ~68 KB
    cudaFuncSetAttribute(attn_kernel,
                         cudaFuncAttributeMaxDynamicSharedMemorySize,
                         (int)smem_bytes);
    attn_kernel<<<dim3(NH*BATCH, SEQ/64), 256, smem_bytes>>>(Qp, Kp, Vp, Op);

    gemm_bias<<<gg, 256>>>(Op, Wp, bp, out, MTOT, ND, ND);
}

// round 4
// speedup vs baseline: 1.5137x; 1.5137x over previous
#include <cuda_runtime.h>
#include <cuda_bf16.h>
#include <math.h>
#include <stdint.h>

#define ND   1024
#define NH   16
#define HD   64
#define SEQ  2048
#define BATCH 4
#define MTOT (BATCH*SEQ)   // 8192

// ---------------- device-global scratch (allocation-free) -------------------
__device__ float g_Q [(size_t)MTOT*ND];
__device__ float g_K [(size_t)MTOT*ND];
__device__ float g_V [(size_t)MTOT*ND];
__device__ __nv_bfloat16 g_xhi[(size_t)MTOT*ND];
__device__ __nv_bfloat16 g_xlo[(size_t)MTOT*ND];
__device__ __nv_bfloat16 g_whi[4][(size_t)ND*ND];
__device__ __nv_bfloat16 g_wlo[4][(size_t)ND*ND];
__device__ __nv_bfloat16 g_ohi[(size_t)MTOT*ND];
__device__ __nv_bfloat16 g_olo[(size_t)MTOT*ND];

// ---------------- PTX helpers (baseline ISA only: ldmatrix + mma.sync) ------
__device__ __forceinline__ uint32_t smem_u32(const void* p) {
    uint32_t a;
    asm("{ .reg .u64 t; cvta.to.shared.u64 t, %1; cvt.u32.u64 %0, t; }"
        : "=r"(a) : "l"(p));
    return a;
}
__device__ __forceinline__ void ldsm4(uint32_t* r, uint32_t addr) {
    asm volatile("ldmatrix.sync.aligned.m8n8.x4.shared.b16 {%0,%1,%2,%3}, [%4];"
                 : "=r"(r[0]), "=r"(r[1]), "=r"(r[2]), "=r"(r[3]) : "r"(addr));
}
__device__ __forceinline__ void mma_bf16(float* c, const uint32_t* a,
                                         const uint32_t* b) {
    asm volatile(
        "mma.sync.aligned.m16n8k16.row.col.f32.bf16.bf16.f32 "
        "{%0,%1,%2,%3}, {%4,%5,%6,%7}, {%8,%9}, {%0,%1,%2,%3};"
        : "+f"(c[0]), "+f"(c[1]), "+f"(c[2]), "+f"(c[3])
        : "r"(a[0]), "r"(a[1]), "r"(a[2]), "r"(a[3]), "r"(b[0]), "r"(b[1]));
}

// ---------------------------------------------------------------------------
// fp32 -> (bf16 hi, bf16 lo) split.
// ---------------------------------------------------------------------------
__global__ __launch_bounds__(256) void split_f32(
    const float* __restrict__ src, __nv_bfloat16* __restrict__ hi,
    __nv_bfloat16* __restrict__ lo, int n4)
{
    int i = blockIdx.x * blockDim.x + threadIdx.x;
    if (i >= n4) return;
    float4 v = *(const float4*)(src + (size_t)i * 4);
    float vs[4] = {v.x, v.y, v.z, v.w};
    __nv_bfloat16 h[4], l[4];
    #pragma unroll
    for (int j = 0; j < 4; j++) {
        h[j] = __float2bfloat16(vs[j]);
        l[j] = __float2bfloat16(vs[j] - __bfloat162float(h[j]));
    }
    *(uint2*)(hi + (size_t)i * 4) = *(uint2*)h;
    *(uint2*)(lo + (size_t)i * 4) = *(uint2*)l;
}

// ---------------------------------------------------------------------------
// HMMA 3xBF16 GEMM:  C[M,N] = (Ahi+Alo) @ (Bhi+Blo)^T + bias   (fp32 out)
// M=8192, N=1024, K=1024.  128x128 CTA tile, BK=32, 256 threads (8 warps 2x4),
// warp tile 64x32 = 4x4 m16n8k16 fragments.  hi*hi + hi*lo + lo*hi.
// ---------------------------------------------------------------------------
#define SMS 40   // smem row stride in bf16 (32 data + 8 pad)

__global__ __launch_bounds__(256) void gemm_bf16(
    const __nv_bfloat16* __restrict__ Ahi, const __nv_bfloat16* __restrict__ Alo,
    const __nv_bfloat16* __restrict__ Bhi, const __nv_bfloat16* __restrict__ Blo,
    const float* __restrict__ bias, float* __restrict__ C)
{
    __shared__ __nv_bfloat16 sAhi[128*SMS], sAlo[128*SMS];
    __shared__ __nv_bfloat16 sBhi[128*SMS], sBlo[128*SMS];

    const int tid  = threadIdx.x;
    const int lane = tid & 31, wid = tid >> 5;
    const int wm = (wid >> 2) << 6;     // 0 / 64
    const int wn = (wid & 3) << 5;      // 0 / 32 / 64 / 96
    const int m0 = blockIdx.y << 7;
    const int n0 = blockIdx.x << 7;

    float acc[4][4][4] = {};            // [mi][ni][frag]

    // ldmatrix lane address patterns
    const int a_row  = lane & 15;            // row within 16-row tile
    const int a_koff = (lane >> 4) << 3;     // 0 / 8 : k-halves
    const int b_row  = ((lane >> 4) << 3) + (lane & 7);   // n within 16
    const int b_koff = ((lane >> 3) & 1) << 3;            // 0 / 8

    const uint32_t sAhiB = smem_u32(sAhi), sAloB = smem_u32(sAlo);
    const uint32_t sBhiB = smem_u32(sBhi), sBloB = smem_u32(sBlo);

    for (int kb = 0; kb < 32; kb++) {
        const int k0 = kb << 5;
        #pragma unroll
        for (int t = 0; t < 2; t++) {
            const int chunk = tid + (t << 8);          // 0..511
            const int r = chunk >> 2, c = (chunk & 3) << 3;
            const size_t ga = (size_t)(m0 + r) * ND + k0 + c;
            const size_t gb = (size_t)(n0 + r) * ND + k0 + c;
            *(int4*)&sAhi[r*SMS + c] = *(const int4*)(Ahi + ga);
            *(int4*)&sAlo[r*SMS + c] = *(const int4*)(Alo + ga);
            *(int4*)&sBhi[r*SMS + c] = *(const int4*)(Bhi + gb);
            *(int4*)&sBlo[r*SMS + c] = *(const int4*)(Blo + gb);
        }
        __syncthreads();

        #pragma unroll
        for (int ks = 0; ks < 2; ks++) {
            const int kk = ks << 4;
            uint32_t ah[4][4], al[4][4], bh[4][2], bl[4][2];
            #pragma unroll
            for (int mi = 0; mi < 4; mi++) {
                const uint32_t off =
                    (uint32_t)(((wm + (mi<<4) + a_row)*SMS + kk + a_koff) * 2);
                ldsm4(ah[mi], sAhiB + off);
                ldsm4(al[mi], sAloB + off);
            }
            #pragma unroll
            for (int nj = 0; nj < 2; nj++) {
                const uint32_t off =
                    (uint32_t)(((wn + (nj<<4) + b_row)*SMS + kk + b_koff) * 2);
                uint32_t r4[4];
                ldsm4(r4, sBhiB + off);
                bh[nj*2][0]=r4[0]; bh[nj*2][1]=r4[1];
                bh[nj*2+1][0]=r4[2]; bh[nj*2+1][1]=r4[3];
                ldsm4(r4, sBloB + off);
                bl[nj*2][0]=r4[0]; bl[nj*2][1]=r4[1];
                bl[nj*2+1][0]=r4[2]; bl[nj*2+1][1]=r4[3];
            }
            #pragma unroll
            for (int mi = 0; mi < 4; mi++)
                #pragma unroll
                for (int ni = 0; ni < 4; ni++) {
                    mma_bf16(acc[mi][ni], ah[mi], bh[ni]);
                    mma_bf16(acc[mi][ni], ah[mi], bl[ni]);
                    mma_bf16(acc[mi][ni], al[mi], bh[ni]);
                }
        }
        __syncthreads();
    }

    // Epilogue: c frag thread mapping: rows t/4 (+8), cols 2*(t%4) (+1)
    const int er = lane >> 2, ec = (lane & 3) << 1;
    #pragma unroll
    for (int ni = 0; ni < 4; ni++) {
        const int col = n0 + wn + (ni << 3) + ec;
        const float b0 = __ldg(bias + col), b1 = __ldg(bias + col + 1);
        #pragma unroll
        for (int mi = 0; mi < 4; mi++) {
            const int row = m0 + wm + (mi << 4) + er;
            float2 o0 = make_float2(acc[mi][ni][0] + b0, acc[mi][ni][1] + b1);
            float2 o1 = make_float2(acc[mi][ni][2] + b0, acc[mi][ni][3] + b1);
            *(float2*)(C + (size_t)row * ND + col)       = o0;
            *(float2*)(C + (size_t)(row + 8) * ND + col) = o1;
        }
    }
}

// ---------------------------------------------------------------------------
// Flash-style attention (SIMT, fp32) — writes bf16 hi/lo output for final GEMM
// ---------------------------------------------------------------------------
#define SQ_STRIDE 68

__global__ __launch_bounds__(256) void attn_kernel(
    const float* __restrict__ Q, const float* __restrict__ K,
    const float* __restrict__ V,
    __nv_bfloat16* __restrict__ Ohi, __nv_bfloat16* __restrict__ Olo)
{
    extern __shared__ float smem[];
    float* sQ     = smem;
    float* sKt    = sQ  + 64*SQ_STRIDE;
    float* sV     = sKt + 64*64;
    float* sS     = sV  + 64*SQ_STRIDE;
    float* sM     = sS  + 64*SQ_STRIDE;
    float* sL     = sM  + 64;
    float* sScale = sL  + 64;

    const int tid = threadIdx.x;
    const int tx = tid & 15, ty = tid >> 4;
    const int hb = blockIdx.x;
    const int b  = hb & 3, h = hb >> 2;
    const int q0 = blockIdx.y << 6;
    const size_t base = (size_t)b * SEQ * ND + h * HD;

    {
        const int r = tid >> 2;
        const int c = (tid & 3) << 2;
        #pragma unroll
        for (int cc = 0; cc < 4; cc++) {
            const int d = cc*16 + c;
            float4 v = *(const float4*)(Q + base + (size_t)(q0 + r)*ND + d);
            *(float4*)&sQ[r*SQ_STRIDE + d] = v;
        }
    }
    if (tid < 64) { sM[tid] = -1e30f; sL[tid] = 0.f; }
    float accO[4][4] = {};
    __syncthreads();

    for (int k0 = 0; k0 < SEQ; k0 += 64) {
        {
            const int r = tid >> 2;
            const int c = (tid & 3) << 2;
            #pragma unroll
            for (int cc = 0; cc < 4; cc++) {
                const int d = cc*16 + c;
                float4 kv = *(const float4*)(K + base + (size_t)(k0 + r)*ND + d);
                sKt[(d+0)*64 + r] = kv.x;
                sKt[(d+1)*64 + r] = kv.y;
                sKt[(d+2)*64 + r] = kv.z;
                sKt[(d+3)*64 + r] = kv.w;
                float4 vv = *(const float4*)(V + base + (size_t)(k0 + r)*ND + d);
                *(float4*)&sV[r*SQ_STRIDE + d] = vv;
            }
        }
        __syncthreads();

        float s[4][4] = {};
        #pragma unroll
        for (int dd = 0; dd < 64; dd++) {
            float a[4], bb[4];
            #pragma unroll
            for (int i = 0; i < 4; i++) a[i] = sQ[(ty*4+i)*SQ_STRIDE + dd];
            *(float4*)bb = *(const float4*)&sKt[dd*64 + (tx<<2)];
            #pragma unroll
            for (int i = 0; i < 4; i++)
                #pragma unroll
                for (int j = 0; j < 4; j++)
                    s[i][j] += a[i] * bb[j];
        }
        #pragma unroll
        for (int i = 0; i < 4; i++)
            *(float4*)&sS[(ty*4+i)*SQ_STRIDE + (tx<<2)] =
                make_float4(s[i][0], s[i][1], s[i][2], s[i][3]);
        __syncthreads();

        {
            const int row = tid >> 2, seg = tid & 3;
            float mx = -1e30f;
            #pragma unroll
            for (int c2 = 0; c2 < 16; c2++)
                mx = fmaxf(mx, sS[row*SQ_STRIDE + seg*16 + c2]);
            mx = fmaxf(mx, __shfl_xor_sync(0xffffffffu, mx, 1));
            mx = fmaxf(mx, __shfl_xor_sync(0xffffffffu, mx, 2));
            const float mold = sM[row];
            const float mnew = fmaxf(mold, mx);
            float sum = 0.f;
            #pragma unroll
            for (int c2 = 0; c2 < 16; c2++) {
                float p = __expf(sS[row*SQ_STRIDE + seg*16 + c2] - mnew);
                sS[row*SQ_STRIDE + seg*16 + c2] = p;
                sum += p;
            }
            sum += __shfl_xor_sync(0xffffffffu, sum, 1);
            sum += __shfl_xor_sync(0xffffffffu, sum, 2);
            if (seg == 0) {
                const float sc = __expf(mold - mnew);
                sScale[row] = sc;
                sM[row] = mnew;
                sL[row] = sL[row] * sc + sum;
            }
        }
        __syncthreads();

        #pragma unroll
        for (int i = 0; i < 4; i++) {
            const float sc = sScale[ty*4+i];
            #pragma unroll
            for (int j = 0; j < 4; j++) accO[i][j] *= sc;
        }
        #pragma unroll
        for (int kk = 0; kk < 64; kk++) {
            float p[4], vv[4];
            #pragma unroll
            for (int i = 0; i < 4; i++) p[i] = sS[(ty*4+i)*SQ_STRIDE + kk];
            *(float4*)vv = *(const float4*)&sV[kk*SQ_STRIDE + (tx<<2)];
            #pragma unroll
            for (int i = 0; i < 4; i++)
                #pragma unroll
                for (int j = 0; j < 4; j++)
                    accO[i][j] += p[i] * vv[j];
        }
        __syncthreads();
    }

    #pragma unroll
    for (int i = 0; i < 4; i++) {
        const int q = q0 + ty*4 + i;
        const float inv = 1.0f / sL[ty*4+i];
        const size_t rowoff = base + (size_t)q*ND + (tx<<2);
        __nv_bfloat16 hs[4], ls[4];
        #pragma unroll
        for (int j = 0; j < 4; j++) {
            float o = accO[i][j] * inv;
            hs[j] = __float2bfloat16(o);
            ls[j] = __float2bfloat16(o - __bfloat162float(hs[j]));
        }
        *(uint2*)(Ohi + rowoff) = *(uint2*)hs;
        *(uint2*)(Olo + rowoff) = *(uint2*)ls;
    }
}

// ---------------------------------------------------------------------------
extern "C" void kernel_launch(void* const* d_in, const int* in_sizes, int n_in,
                              void* d_out, int out_size)
{
    const float* x  = (const float*)d_in[0];
    const float* Wq = (const float*)d_in[1];
    const float* bq = (const float*)d_in[2];
    const float* Wk = (const float*)d_in[3];
    const float* bk = (const float*)d_in[4];
    const float* Wv = (const float*)d_in[5];
    const float* bv = (const float*)d_in[6];
    const float* Wp = (const float*)d_in[7];
    const float* bp = (const float*)d_in[8];
    float* out = (float*)d_out;

    float *Qp, *Kp, *Vp;
    __nv_bfloat16 *xhi, *xlo, *whi, *wlo, *ohi, *olo;
    cudaGetSymbolAddress((void**)&Qp,  g_Q);
    cudaGetSymbolAddress((void**)&Kp,  g_K);
    cudaGetSymbolAddress((void**)&Vp,  g_V);
    cudaGetSymbolAddress((void**)&xhi, g_xhi);
    cudaGetSymbolAddress((void**)&xlo, g_xlo);
    cudaGetSymbolAddress((void**)&whi, g_whi);
    cudaGetSymbolAddress((void**)&wlo, g_wlo);
    cudaGetSymbolAddress((void**)&ohi, g_ohi);
    cudaGetSymbolAddress((void**)&olo, g_olo);

    const size_t WSZ = (size_t)ND * ND;

    // fp32 -> bf16 hi/lo splits
    split_f32<<<(MTOT*ND/4 + 255)/256, 256>>>(x,  xhi, xlo, MTOT*ND/4);
    split_f32<<<(ND*ND/4 + 255)/256, 256>>>(Wq, whi + 0*WSZ, wlo + 0*WSZ, ND*ND/4);
    split_f32<<<(ND*ND/4 + 255)/256, 256>>>(Wk, whi + 1*WSZ, wlo + 1*WSZ, ND*ND/4);
    split_f32<<<(ND*ND/4 + 255)/256, 256>>>(Wv, whi + 2*WSZ, wlo + 2*WSZ, ND*ND/4);
    split_f32<<<(ND*ND/4 + 255)/256, 256>>>(Wp, whi + 3*WSZ, wlo + 3*WSZ, ND*ND/4);

    const dim3 gg(ND/128, MTOT/128);   // (8, 64)
    gemm_bf16<<<gg, 256>>>(xhi, xlo, whi + 0*WSZ, wlo + 0*WSZ, bq, Qp);
    gemm_bf16<<<gg, 256>>>(xhi, xlo, whi + 1*WSZ, wlo + 1*WSZ, bk, Kp);
    gemm_bf16<<<gg, 256>>>(xhi, xlo, whi + 2*WSZ, wlo + 2*WSZ, bv, Vp);

    const size_t attn_smem =
        (size_t)(64*SQ_STRIDE*3 + 64*64 + 3*64) * sizeof(float);
    cudaFuncSetAttribute(attn_kernel,
                         cudaFuncAttributeMaxDynamicSharedMemorySize,
                         (int)attn_smem);
    attn_kernel<<<dim3(NH*BATCH, SEQ/64), 256, attn_smem>>>(Qp, Kp, Vp, ohi, olo);

    gemm_bf16<<<gg, 256>>>(ohi, olo, whi + 3*WSZ, wlo + 3*WSZ, bp, out);
}

// round 6
// speedup vs baseline: 2.6152x; 1.7277x over previous
#include <cuda_runtime.h>
#include <cuda_bf16.h>
#include <math.h>
#include <stdint.h>

#define ND   1024
#define NH   16
#define HD   64
#define SEQ  2048
#define BATCH 4
#define MTOT (BATCH*SEQ)   // 8192

typedef __nv_bfloat16 bf16;

// ---------------- device-global scratch (allocation-free) -------------------
__device__ bf16 g_xhi[(size_t)MTOT*ND];
__device__ bf16 g_xlo[(size_t)MTOT*ND];
__device__ bf16 g_whi[4][(size_t)ND*ND];
__device__ bf16 g_wlo[4][(size_t)ND*ND];
__device__ bf16 g_qhi[(size_t)MTOT*ND];
__device__ bf16 g_qlo[(size_t)MTOT*ND];
__device__ bf16 g_khi[(size_t)MTOT*ND];
__device__ bf16 g_klo[(size_t)MTOT*ND];
__device__ bf16 g_vhi[(size_t)MTOT*ND];
__device__ bf16 g_vlo[(size_t)MTOT*ND];
__device__ bf16 g_ohi[(size_t)MTOT*ND];
__device__ bf16 g_olo[(size_t)MTOT*ND];

// ---------------- PTX helpers (baseline ISA only) ---------------------------
__device__ __forceinline__ uint32_t smem_u32(const void* p) {
    uint32_t a;
    asm("{ .reg .u64 t; cvta.to.shared.u64 t, %1; cvt.u32.u64 %0, t; }"
        : "=r"(a) : "l"(p));
    return a;
}
__device__ __forceinline__ void ldsm4(uint32_t* r, uint32_t addr) {
    asm volatile("ldmatrix.sync.aligned.m8n8.x4.shared.b16 {%0,%1,%2,%3}, [%4];"
                 : "=r"(r[0]), "=r"(r[1]), "=r"(r[2]), "=r"(r[3]) : "r"(addr));
}
__device__ __forceinline__ void ldsm4t(uint32_t* r, uint32_t addr) {
    asm volatile("ldmatrix.sync.aligned.m8n8.x4.trans.shared.b16 {%0,%1,%2,%3}, [%4];"
                 : "=r"(r[0]), "=r"(r[1]), "=r"(r[2]), "=r"(r[3]) : "r"(addr));
}
__device__ __forceinline__ void mma_bf16(float* c, const uint32_t* a,
                                         const uint32_t* b) {
    asm volatile(
        "mma.sync.aligned.m16n8k16.row.col.f32.bf16.bf16.f32 "
        "{%0,%1,%2,%3}, {%4,%5,%6,%7}, {%8,%9}, {%0,%1,%2,%3};"
        : "+f"(c[0]), "+f"(c[1]), "+f"(c[2]), "+f"(c[3])
        : "r"(a[0]), "r"(a[1]), "r"(a[2]), "r"(a[3]), "r"(b[0]), "r"(b[1]));
}
// pack two fp32 -> bf16x2 (lo element in bits [15:0])
__device__ __forceinline__ uint32_t pk2(float lo, float hi) {
    uint32_t r;
    asm("cvt.rn.bf16x2.f32 %0, %1, %2;" : "=r"(r) : "f"(hi), "f"(lo));
    return r;
}
__device__ __forceinline__ float bfl(uint32_t u) {   // low bf16 -> float
    return __uint_as_float(u << 16);
}
__device__ __forceinline__ float bfh(uint32_t u) {   // high bf16 -> float
    return __uint_as_float(u & 0xffff0000u);
}

// ---------------------------------------------------------------------------
// fp32 -> (bf16 hi, bf16 lo) split (for x and weights only)
// ---------------------------------------------------------------------------
__global__ __launch_bounds__(256) void split_f32(
    const float* __restrict__ src, bf16* __restrict__ hi,
    bf16* __restrict__ lo, int n4)
{
    int i = blockIdx.x * blockDim.x + threadIdx.x;
    if (i >= n4) return;
    float4 v = *(const float4*)(src + (size_t)i * 4);
    float vs[4] = {v.x, v.y, v.z, v.w};
    uint32_t h[2], l[2];
    #pragma unroll
    for (int j = 0; j < 2; j++) {
        h[j] = pk2(vs[2*j], vs[2*j+1]);
        l[j] = pk2(vs[2*j] - bfl(h[j]), vs[2*j+1] - bfh(h[j]));
    }
    *(uint2*)(hi + (size_t)i * 4) = make_uint2(h[0], h[1]);
    *(uint2*)(lo + (size_t)i * 4) = make_uint2(l[0], l[1]);
}

// ---------------------------------------------------------------------------
// HMMA 3xBF16 GEMM:  C = (Ahi+Alo) @ (Bhi+Blo)^T + bias
// OUTMODE 0: fp32 C.  OUTMODE 1: bf16 hi/lo split C.
// 128x128 CTA tile, BK=32, 256 threads (8 warps 2x4), warp 64x32.
// ---------------------------------------------------------------------------
#define SMS 40

template<int OUTMODE>
__global__ __launch_bounds__(256) void gemm_bf16(
    const bf16* __restrict__ Ahi, const bf16* __restrict__ Alo,
    const bf16* __restrict__ Bhi, const bf16* __restrict__ Blo,
    const float* __restrict__ bias, float* __restrict__ C,
    bf16* __restrict__ Chi, bf16* __restrict__ Clo)
{
    __shared__ bf16 sAhi[128*SMS], sAlo[128*SMS];
    __shared__ bf16 sBhi[128*SMS], sBlo[128*SMS];

    const int tid  = threadIdx.x;
    const int lane = tid & 31, wid = tid >> 5;
    const int wm = (wid >> 2) << 6;
    const int wn = (wid & 3) << 5;
    const int m0 = blockIdx.y << 7;
    const int n0 = blockIdx.x << 7;

    float acc[4][4][4] = {};

    const int a_row  = lane & 15;
    const int a_koff = (lane >> 4) << 3;
    const int b_row  = ((lane >> 4) << 3) + (lane & 7);
    const int b_koff = ((lane >> 3) & 1) << 3;

    const uint32_t sAhiB = smem_u32(sAhi), sAloB = smem_u32(sAlo);
    const uint32_t sBhiB = smem_u32(sBhi), sBloB = smem_u32(sBlo);

    for (int kb = 0; kb < 32; kb++) {
        const int k0 = kb << 5;
        #pragma unroll
        for (int t = 0; t < 2; t++) {
            const int chunk = tid + (t << 8);
            const int r = chunk >> 2, c = (chunk & 3) << 3;
            const size_t ga = (size_t)(m0 + r) * ND + k0 + c;
            const size_t gb = (size_t)(n0 + r) * ND + k0 + c;
            *(int4*)&sAhi[r*SMS + c] = *(const int4*)(Ahi + ga);
            *(int4*)&sAlo[r*SMS + c] = *(const int4*)(Alo + ga);
            *(int4*)&sBhi[r*SMS + c] = *(const int4*)(Bhi + gb);
            *(int4*)&sBlo[r*SMS + c] = *(const int4*)(Blo + gb);
        }
        __syncthreads();

        #pragma unroll
        for (int ks = 0; ks < 2; ks++) {
            const int kk = ks << 4;
            uint32_t ah[4][4], al[4][4], bh[4][2], bl[4][2];
            #pragma unroll
            for (int mi = 0; mi < 4; mi++) {
                const uint32_t off =
                    (uint32_t)(((wm + (mi<<4) + a_row)*SMS + kk + a_koff) * 2);
                ldsm4(ah[mi], sAhiB + off);
                ldsm4(al[mi], sAloB + off);
            }
            #pragma unroll
            for (int nj = 0; nj < 2; nj++) {
                const uint32_t off =
                    (uint32_t)(((wn + (nj<<4) + b_row)*SMS + kk + b_koff) * 2);
                uint32_t r4[4];
                ldsm4(r4, sBhiB + off);
                bh[nj*2][0]=r4[0]; bh[nj*2][1]=r4[1];
                bh[nj*2+1][0]=r4[2]; bh[nj*2+1][1]=r4[3];
                ldsm4(r4, sBloB + off);
                bl[nj*2][0]=r4[0]; bl[nj*2][1]=r4[1];
                bl[nj*2+1][0]=r4[2]; bl[nj*2+1][1]=r4[3];
            }
            #pragma unroll
            for (int mi = 0; mi < 4; mi++)
                #pragma unroll
                for (int ni = 0; ni < 4; ni++) {
                    mma_bf16(acc[mi][ni], ah[mi], bh[ni]);
                    mma_bf16(acc[mi][ni], ah[mi], bl[ni]);
                    mma_bf16(acc[mi][ni], al[mi], bh[ni]);
                }
        }
        __syncthreads();
    }

    const int er = lane >> 2, ec = (lane & 3) << 1;
    #pragma unroll
    for (int ni = 0; ni < 4; ni++) {
        const int col = n0 + wn + (ni << 3) + ec;
        const float b0 = __ldg(bias + col), b1 = __ldg(bias + col + 1);
        #pragma unroll
        for (int mi = 0; mi < 4; mi++) {
            const int row = m0 + wm + (mi << 4) + er;
            const float v0 = acc[mi][ni][0] + b0, v1 = acc[mi][ni][1] + b1;
            const float v2 = acc[mi][ni][2] + b0, v3 = acc[mi][ni][3] + b1;
            if (OUTMODE == 0) {
                *(float2*)(C + (size_t)row * ND + col)       = make_float2(v0, v1);
                *(float2*)(C + (size_t)(row + 8) * ND + col) = make_float2(v2, v3);
            } else {
                uint32_t h0 = pk2(v0, v1);
                uint32_t l0 = pk2(v0 - bfl(h0), v1 - bfh(h0));
                uint32_t h1 = pk2(v2, v3);
                uint32_t l1 = pk2(v2 - bfl(h1), v3 - bfh(h1));
                *(uint32_t*)(Chi + (size_t)row * ND + col)       = h0;
                *(uint32_t*)(Clo + (size_t)row * ND + col)       = l0;
                *(uint32_t*)(Chi + (size_t)(row + 8) * ND + col) = h1;
                *(uint32_t*)(Clo + (size_t)(row + 8) * ND + col) = l1;
            }
        }
    }
}

// ---------------------------------------------------------------------------
// Tensor-core flash attention.
// Grid: (qtile=16, hb=64).  256 threads = 8 warps; warp = 16 query rows.
// K tile = 64 keys.  S = QK^T via 3-term split; O += P V via 3-term split.
// No 1/sqrt(d) scaling (matches reference).
// ---------------------------------------------------------------------------
#define APAD 72   // bf16 row stride (64 data + 8 pad)

__global__ __launch_bounds__(256) void attn_mma(
    const bf16* __restrict__ Qhi, const bf16* __restrict__ Qlo,
    const bf16* __restrict__ Khi, const bf16* __restrict__ Klo,
    const bf16* __restrict__ Vhi, const bf16* __restrict__ Vlo,
    bf16* __restrict__ Ohi, bf16* __restrict__ Olo)
{
    extern __shared__ bf16 sm[];
    bf16* sQh = sm;                 // 128 x APAD
    bf16* sQl = sQh + 128*APAD;
    bf16* sKh = sQl + 128*APAD;     // 64 x APAD
    bf16* sKl = sKh + 64*APAD;
    bf16* sVh = sKl + 64*APAD;
    bf16* sVl = sVh + 64*APAD;

    const int tid = threadIdx.x;
    const int lane = tid & 31, wid = tid >> 5;
    const int hb = blockIdx.y;
    const int b  = hb & 3, h = hb >> 2;
    const int q0 = blockIdx.x << 7;
    const size_t base = (size_t)b * SEQ * ND + h * HD;

    // --- load Q tile (128 x 64 hi/lo) ---
    for (int i = tid; i < 128*8; i += 256) {
        const int r = i >> 3, c8 = (i & 7) << 3;
        const size_t g = base + (size_t)(q0 + r) * ND + c8;
        *(int4*)&sQh[r*APAD + c8] = *(const int4*)(Qhi + g);
        *(int4*)&sQl[r*APAD + c8] = *(const int4*)(Qlo + g);
    }
    __syncthreads();

    // --- Q fragments (hoisted) ---
    const int a_row  = lane & 15;
    const int a_koff = (lane >> 4) << 3;
    uint32_t qh[4][4], ql[4][4];
    #pragma unroll
    for (int ks = 0; ks < 4; ks++) {
        const uint32_t off =
            (uint32_t)(((wid*16 + a_row)*APAD + ks*16 + a_koff) * 2);
        ldsm4(qh[ks], smem_u32(sQh) + off);
        ldsm4(ql[ks], smem_u32(sQl) + off);
    }

    const int b_row  = ((lane >> 4) << 3) + (lane & 7);
    const int b_koff = ((lane >> 3) & 1) << 3;
    const int v_krow = (((lane >> 3) & 1) << 3) + (lane & 7);
    const int v_doff = (lane >> 4) << 3;
    const uint32_t sKhB = smem_u32(sKh), sKlB = smem_u32(sKl);
    const uint32_t sVhB = smem_u32(sVh), sVlB = smem_u32(sVl);

    float m0v = -1e30f, m1v = -1e30f, l0v = 0.f, l1v = 0.f;
    float o[8][4] = {};

    for (int k0 = 0; k0 < SEQ; k0 += 64) {
        // --- load K/V tiles ---
        for (int i = tid; i < 64*8; i += 256) {
            const int r = i >> 3, c8 = (i & 7) << 3;
            const size_t g = base + (size_t)(k0 + r) * ND + c8;
            *(int4*)&sKh[r*APAD + c8] = *(const int4*)(Khi + g);
            *(int4*)&sKl[r*APAD + c8] = *(const int4*)(Klo + g);
            *(int4*)&sVh[r*APAD + c8] = *(const int4*)(Vhi + g);
            *(int4*)&sVl[r*APAD + c8] = *(const int4*)(Vlo + g);
        }
        __syncthreads();

        // --- S = Q K^T  (16 x 64 per warp) ---
        float s[8][4] = {};
        #pragma unroll
        for (int ks = 0; ks < 4; ks++) {
            #pragma unroll
            for (int ng = 0; ng < 4; ng++) {
                const uint32_t off =
                    (uint32_t)(((ng*16 + b_row)*APAD + ks*16 + b_koff) * 2);
                uint32_t kbh[4], kbl[4];
                ldsm4(kbh, sKhB + off);
                ldsm4(kbl, sKlB + off);
                mma_bf16(s[ng*2],   qh[ks], kbh);
                mma_bf16(s[ng*2+1], qh[ks], kbh + 2);
                mma_bf16(s[ng*2],   qh[ks], kbl);
                mma_bf16(s[ng*2+1], qh[ks], kbl + 2);
                mma_bf16(s[ng*2],   ql[ks], kbh);
                mma_bf16(s[ng*2+1], ql[ks], kbh + 2);
            }
        }

        // --- online softmax (rows r=lane>>2 and r+8) ---
        float mx0 = m0v, mx1 = m1v;
        #pragma unroll
        for (int f = 0; f < 8; f++) {
            mx0 = fmaxf(mx0, fmaxf(s[f][0], s[f][1]));
            mx1 = fmaxf(mx1, fmaxf(s[f][2], s[f][3]));
        }
        mx0 = fmaxf(mx0, __shfl_xor_sync(0xffffffffu, mx0, 1));
        mx0 = fmaxf(mx0, __shfl_xor_sync(0xffffffffu, mx0, 2));
        mx1 = fmaxf(mx1, __shfl_xor_sync(0xffffffffu, mx1, 1));
        mx1 = fmaxf(mx1, __shfl_xor_sync(0xffffffffu, mx1, 2));
        const float sc0 = __expf(m0v - mx0);
        const float sc1 = __expf(m1v - mx1);
        float sum0 = 0.f, sum1 = 0.f;
        #pragma unroll
        for (int f = 0; f < 8; f++) {
            s[f][0] = __expf(s[f][0] - mx0);
            s[f][1] = __expf(s[f][1] - mx0);
            s[f][2] = __expf(s[f][2] - mx1);
            s[f][3] = __expf(s[f][3] - mx1);
            sum0 += s[f][0] + s[f][1];
            sum1 += s[f][2] + s[f][3];
        }
        sum0 += __shfl_xor_sync(0xffffffffu, sum0, 1);
        sum0 += __shfl_xor_sync(0xffffffffu, sum0, 2);
        sum1 += __shfl_xor_sync(0xffffffffu, sum1, 1);
        sum1 += __shfl_xor_sync(0xffffffffu, sum1, 2);
        l0v = l0v * sc0 + sum0;  m0v = mx0;
        l1v = l1v * sc1 + sum1;  m1v = mx1;
        #pragma unroll
        for (int f = 0; f < 8; f++) {
            o[f][0] *= sc0; o[f][1] *= sc0;
            o[f][2] *= sc1; o[f][3] *= sc1;
        }

        // --- pack P -> bf16 hi/lo A-fragments ---
        uint32_t ph[4][4], pl[4][4];
        #pragma unroll
        for (int ksp = 0; ksp < 4; ksp++) {
            const float* e = s[2*ksp];
            const float* oq = s[2*ksp+1];
            ph[ksp][0] = pk2(e[0], e[1]);
            pl[ksp][0] = pk2(e[0] - bfl(ph[ksp][0]), e[1] - bfh(ph[ksp][0]));
            ph[ksp][1] = pk2(e[2], e[3]);
            pl[ksp][1] = pk2(e[2] - bfl(ph[ksp][1]), e[3] - bfh(ph[ksp][1]));
            ph[ksp][2] = pk2(oq[0], oq[1]);
            pl[ksp][2] = pk2(oq[0] - bfl(ph[ksp][2]), oq[1] - bfh(ph[ksp][2]));
            ph[ksp][3] = pk2(oq[2], oq[3]);
            pl[ksp][3] = pk2(oq[2] - bfl(ph[ksp][3]), oq[3] - bfh(ph[ksp][3]));
        }

        // --- O += P V ---
        #pragma unroll
        for (int ksp = 0; ksp < 4; ksp++) {
            #pragma unroll
            for (int dg = 0; dg < 4; dg++) {
                const uint32_t off =
                    (uint32_t)(((ksp*16 + v_krow)*APAD + dg*16 + v_doff) * 2);
                uint32_t vbh[4], vbl[4];
                ldsm4t(vbh, sVhB + off);
                ldsm4t(vbl, sVlB + off);
                mma_bf16(o[dg*2],   ph[ksp], vbh);
                mma_bf16(o[dg*2+1], ph[ksp], vbh + 2);
                mma_bf16(o[dg*2],   ph[ksp], vbl);
                mma_bf16(o[dg*2+1], ph[ksp], vbl + 2);
                mma_bf16(o[dg*2],   pl[ksp], vbh);
                mma_bf16(o[dg*2+1], pl[ksp], vbh + 2);
            }
        }
        __syncthreads();
    }

    // --- normalize + write hi/lo bf16 output ---
    const float inv0 = 1.0f / l0v, inv1 = 1.0f / l1v;
    const int r0 = q0 + wid*16 + (lane >> 2);
    const int ec = (lane & 3) << 1;
    #pragma unroll
    for (int dg = 0; dg < 8; dg++) {
        const int col = dg*8 + ec;
        const size_t g0 = base + (size_t)r0 * ND + col;
        const size_t g1 = base + (size_t)(r0 + 8) * ND + col;
        const float v0 = o[dg][0]*inv0, v1 = o[dg][1]*inv0;
        const float v2 = o[dg][2]*inv1, v3 = o[dg][3]*inv1;
        uint32_t h0 = pk2(v0, v1);
        uint32_t l0 = pk2(v0 - bfl(h0), v1 - bfh(h0));
        uint32_t h1 = pk2(v2, v3);
        uint32_t l1 = pk2(v2 - bfl(h1), v3 - bfh(h1));
        *(uint32_t*)(Ohi + g0) = h0;
        *(uint32_t*)(Olo + g0) = l0;
        *(uint32_t*)(Ohi + g1) = h1;
        *(uint32_t*)(Olo + g1) = l1;
    }
}

// ---------------------------------------------------------------------------
extern "C" void kernel_launch(void* const* d_in, const int* in_sizes, int n_in,
                              void* d_out, int out_size)
{
    const float* x  = (const float*)d_in[0];
    const float* Wq = (const float*)d_in[1];
    const float* bq = (const float*)d_in[2];
    const float* Wk = (const float*)d_in[3];
    const float* bk = (const float*)d_in[4];
    const float* Wv = (const float*)d_in[5];
    const float* bv = (const float*)d_in[6];
    const float* Wp = (const float*)d_in[7];
    const float* bp = (const float*)d_in[8];
    float* out = (float*)d_out;

    bf16 *xhi, *xlo, *whi, *wlo;
    bf16 *qhi, *qlo, *khi, *klo, *vhi, *vlo, *ohi, *olo;
    cudaGetSymbolAddress((void**)&xhi, g_xhi);
    cudaGetSymbolAddress((void**)&xlo, g_xlo);
    cudaGetSymbolAddress((void**)&whi, g_whi);
    cudaGetSymbolAddress((void**)&wlo, g_wlo);
    cudaGetSymbolAddress((void**)&qhi, g_qhi);
    cudaGetSymbolAddress((void**)&qlo, g_qlo);
    cudaGetSymbolAddress((void**)&khi, g_khi);
    cudaGetSymbolAddress((void**)&klo, g_klo);
    cudaGetSymbolAddress((void**)&vhi, g_vhi);
    cudaGetSymbolAddress((void**)&vlo, g_vlo);
    cudaGetSymbolAddress((void**)&ohi, g_ohi);
    cudaGetSymbolAddress((void**)&olo, g_olo);

    const size_t WSZ = (size_t)ND * ND;

    split_f32<<<(MTOT*ND/4 + 255)/256, 256>>>(x,  xhi, xlo, MTOT*ND/4);
    split_f32<<<(ND*ND/4 + 255)/256, 256>>>(Wq, whi + 0*WSZ, wlo + 0*WSZ, ND*ND/4);
    split_f32<<<(ND*ND/4 + 255)/256, 256>>>(Wk, whi + 1*WSZ, wlo + 1*WSZ, ND*ND/4);
    split_f32<<<(ND*ND/4 + 255)/256, 256>>>(Wv, whi + 2*WSZ, wlo + 2*WSZ, ND*ND/4);
    split_f32<<<(ND*ND/4 + 255)/256, 256>>>(Wp, whi + 3*WSZ, wlo + 3*WSZ, ND*ND/4);

    const dim3 gg(ND/128, MTOT/128);   // (8, 64)
    gemm_bf16<1><<<gg, 256>>>(xhi, xlo, whi + 0*WSZ, wlo + 0*WSZ, bq,
                              nullptr, qhi, qlo);
    gemm_bf16<1><<<gg, 256>>>(xhi, xlo, whi + 1*WSZ, wlo + 1*WSZ, bk,
                              nullptr, khi, klo);
    gemm_bf16<1><<<gg, 256>>>(xhi, xlo, whi + 2*WSZ, wlo + 2*WSZ, bv,
                              nullptr, vhi, vlo);

    const size_t attn_smem = (size_t)(128*APAD*2 + 64*APAD*4) * sizeof(bf16);
    cudaFuncSetAttribute(attn_mma,
                         cudaFuncAttributeMaxDynamicSharedMemorySize,
                         (int)attn_smem);
    attn_mma<<<dim3(SEQ/128, NH*BATCH), 256, attn_smem>>>(
        qhi, qlo, khi, klo, vhi, vlo, ohi, olo);

    gemm_bf16<0><<<gg, 256>>>(ohi, olo, whi + 3*WSZ, wlo + 3*WSZ, bp,
                              out, nullptr, nullptr);
}

// round 8
// speedup vs baseline: 3.2874x; 1.2570x over previous
#include <cuda_runtime.h>
#include <cuda_bf16.h>
#include <math.h>
#include <stdint.h>

#define ND   1024
#define NH   16
#define HD   64
#define SEQ  2048
#define BATCH 4
#define MTOT (BATCH*SEQ)   // 8192

typedef __nv_bfloat16 bf16;

// ---------------- device-global scratch (allocation-free) -------------------
__device__ bf16 g_xhi[(size_t)MTOT*ND];
__device__ bf16 g_xlo[(size_t)MTOT*ND];
__device__ bf16 g_whi[4][(size_t)ND*ND];
__device__ bf16 g_wlo[4][(size_t)ND*ND];
__device__ bf16 g_qhi[(size_t)MTOT*ND];
__device__ bf16 g_qlo[(size_t)MTOT*ND];
__device__ bf16 g_khi[(size_t)MTOT*ND];
__device__ bf16 g_klo[(size_t)MTOT*ND];
__device__ bf16 g_vhi[(size_t)MTOT*ND];
__device__ bf16 g_vlo[(size_t)MTOT*ND];
__device__ bf16 g_ohi[(size_t)MTOT*ND];
__device__ bf16 g_olo[(size_t)MTOT*ND];

// ---------------- PTX helpers (baseline ISA only) ---------------------------
__device__ __forceinline__ uint32_t smem_u32(const void* p) {
    uint32_t a;
    asm("{ .reg .u64 t; cvta.to.shared.u64 t, %1; cvt.u32.u64 %0, t; }"
        : "=r"(a) : "l"(p));
    return a;
}
__device__ __forceinline__ void ldsm4(uint32_t* r, uint32_t addr) {
    asm volatile("ldmatrix.sync.aligned.m8n8.x4.shared.b16 {%0,%1,%2,%3}, [%4];"
                 : "=r"(r[0]), "=r"(r[1]), "=r"(r[2]), "=r"(r[3]) : "r"(addr));
}
__device__ __forceinline__ void ldsm4t(uint32_t* r, uint32_t addr) {
    asm volatile("ldmatrix.sync.aligned.m8n8.x4.trans.shared.b16 {%0,%1,%2,%3}, [%4];"
                 : "=r"(r[0]), "=r"(r[1]), "=r"(r[2]), "=r"(r[3]) : "r"(addr));
}
__device__ __forceinline__ void mma_bf16(float* c, const uint32_t* a,
                                         const uint32_t* b) {
    asm volatile(
        "mma.sync.aligned.m16n8k16.row.col.f32.bf16.bf16.f32 "
        "{%0,%1,%2,%3}, {%4,%5,%6,%7}, {%8,%9}, {%0,%1,%2,%3};"
        : "+f"(c[0]), "+f"(c[1]), "+f"(c[2]), "+f"(c[3])
        : "r"(a[0]), "r"(a[1]), "r"(a[2]), "r"(a[3]), "r"(b[0]), "r"(b[1]));
}
__device__ __forceinline__ void cp16(uint32_t saddr, const void* g) {
    asm volatile("cp.async.cg.shared.global [%0], [%1], 16;"
                 :: "r"(saddr), "l"(g) : "memory");
}
__device__ __forceinline__ void cp_commit() {
    asm volatile("cp.async.commit_group;" ::: "memory");
}
template<int N>
__device__ __forceinline__ void cp_wait() {
    asm volatile("cp.async.wait_group %0;" :: "n"(N) : "memory");
}
// pack two fp32 -> bf16x2 (lo element in bits [15:0])
__device__ __forceinline__ uint32_t pk2(float lo, float hi) {
    uint32_t r;
    asm("cvt.rn.bf16x2.f32 %0, %1, %2;" : "=r"(r) : "f"(hi), "f"(lo));
    return r;
}
__device__ __forceinline__ float bfl(uint32_t u) { return __uint_as_float(u << 16); }
__device__ __forceinline__ float bfh(uint32_t u) { return __uint_as_float(u & 0xffff0000u); }

// ---------------------------------------------------------------------------
// fp32 -> (bf16 hi, bf16 lo) split (x and weights)
// ---------------------------------------------------------------------------
__global__ __launch_bounds__(256) void split_f32(
    const float* __restrict__ src, bf16* __restrict__ hi,
    bf16* __restrict__ lo, int n4)
{
    int i = blockIdx.x * blockDim.x + threadIdx.x;
    if (i >= n4) return;
    float4 v = *(const float4*)(src + (size_t)i * 4);
    float vs[4] = {v.x, v.y, v.z, v.w};
    uint32_t h[2], l[2];
    #pragma unroll
    for (int j = 0; j < 2; j++) {
        h[j] = pk2(vs[2*j], vs[2*j+1]);
        l[j] = pk2(vs[2*j] - bfl(h[j]), vs[2*j+1] - bfh(h[j]));
    }
    *(uint2*)(hi + (size_t)i * 4) = make_uint2(h[0], h[1]);
    *(uint2*)(lo + (size_t)i * 4) = make_uint2(l[0], l[1]);
}

// ---------------------------------------------------------------------------
// HMMA 3xBF16 GEMM, 2-stage cp.async pipeline.
// C = (Ahi+Alo)@(Bhi+Blo)^T + bias.  128x128 CTA, BK=32, 8 warps (2x4).
// ---------------------------------------------------------------------------
#define SMS 40
#define G_TILE (128*SMS)          // elems per matrix per stage
#define G_STG  (4*G_TILE)         // elems per stage

template<int OUTMODE>
__global__ __launch_bounds__(256) void gemm_bf16(
    const bf16* __restrict__ Ahi, const bf16* __restrict__ Alo,
    const bf16* __restrict__ Bhi, const bf16* __restrict__ Blo,
    const float* __restrict__ bias, float* __restrict__ C,
    bf16* __restrict__ Chi, bf16* __restrict__ Clo)
{
    extern __shared__ bf16 gsm[];
    const uint32_t smB = smem_u32(gsm);

    const int tid  = threadIdx.x;
    const int lane = tid & 31, wid = tid >> 5;
    const int wm = (wid >> 2) << 6;
    const int wn = (wid & 3) << 5;
    const int m0 = blockIdx.y << 7;
    const int n0 = blockIdx.x << 7;

    float acc[4][4][4] = {};

    const int a_row  = lane & 15;
    const int a_koff = (lane >> 4) << 3;
    const int b_row  = ((lane >> 4) << 3) + (lane & 7);
    const int b_koff = ((lane >> 3) & 1) << 3;

    // load-thread mapping: r = tid>>2 (+64), c = (tid&3)*8
    const int lr = tid >> 2, lc = (tid & 3) << 3;
    const uint32_t so0 = (uint32_t)(lr*SMS + lc) * 2;
    const uint32_t so1 = (uint32_t)((lr+64)*SMS + lc) * 2;

    auto load_stage = [&](int stage, int kb) {
        const int k0 = kb << 5;
        const uint32_t sb = smB + (uint32_t)stage * G_STG * 2;
        const size_t ga0 = (size_t)(m0 + lr) * ND + k0 + lc;
        const size_t ga1 = (size_t)(m0 + lr + 64) * ND + k0 + lc;
        const size_t gb0 = (size_t)(n0 + lr) * ND + k0 + lc;
        const size_t gb1 = (size_t)(n0 + lr + 64) * ND + k0 + lc;
        cp16(sb + 0*G_TILE*2 + so0, Ahi + ga0);
        cp16(sb + 0*G_TILE*2 + so1, Ahi + ga1);
        cp16(sb + 1*G_TILE*2 + so0, Alo + ga0);
        cp16(sb + 1*G_TILE*2 + so1, Alo + ga1);
        cp16(sb + 2*G_TILE*2 + so0, Bhi + gb0);
        cp16(sb + 2*G_TILE*2 + so1, Bhi + gb1);
        cp16(sb + 3*G_TILE*2 + so0, Blo + gb0);
        cp16(sb + 3*G_TILE*2 + so1, Blo + gb1);
        cp_commit();
    };

    load_stage(0, 0);

    for (int kb = 0; kb < 32; kb++) {
        if (kb + 1 < 32) { load_stage((kb + 1) & 1, kb + 1); cp_wait<1>(); }
        else             { cp_wait<0>(); }
        __syncthreads();

        const uint32_t sb = smB + (uint32_t)(kb & 1) * G_STG * 2;
        const uint32_t sAhiB = sb, sAloB = sb + G_TILE*2;
        const uint32_t sBhiB = sb + 2*G_TILE*2, sBloB = sb + 3*G_TILE*2;

        #pragma unroll
        for (int ks = 0; ks < 2; ks++) {
            const int kk = ks << 4;
            uint32_t ah[4][4], al[4][4], bh[4][2], bl[4][2];
            #pragma unroll
            for (int mi = 0; mi < 4; mi++) {
                const uint32_t off =
                    (uint32_t)(((wm + (mi<<4) + a_row)*SMS + kk + a_koff) * 2);
                ldsm4(ah[mi], sAhiB + off);
                ldsm4(al[mi], sAloB + off);
            }
            #pragma unroll
            for (int nj = 0; nj < 2; nj++) {
                const uint32_t off =
                    (uint32_t)(((wn + (nj<<4) + b_row)*SMS + kk + b_koff) * 2);
                uint32_t r4[4];
                ldsm4(r4, sBhiB + off);
                bh[nj*2][0]=r4[0]; bh[nj*2][1]=r4[1];
                bh[nj*2+1][0]=r4[2]; bh[nj*2+1][1]=r4[3];
                ldsm4(r4, sBloB + off);
                bl[nj*2][0]=r4[0]; bl[nj*2][1]=r4[1];
                bl[nj*2+1][0]=r4[2]; bl[nj*2+1][1]=r4[3];
            }
            #pragma unroll
            for (int mi = 0; mi < 4; mi++)
                #pragma unroll
                for (int ni = 0; ni < 4; ni++) {
                    mma_bf16(acc[mi][ni], ah[mi], bh[ni]);
                    mma_bf16(acc[mi][ni], ah[mi], bl[ni]);
                    mma_bf16(acc[mi][ni], al[mi], bh[ni]);
                }
        }
        __syncthreads();
    }

    const int er = lane >> 2, ec = (lane & 3) << 1;
    #pragma unroll
    for (int ni = 0; ni < 4; ni++) {
        const int col = n0 + wn + (ni << 3) + ec;
        const float b0 = __ldg(bias + col), b1 = __ldg(bias + col + 1);
        #pragma unroll
        for (int mi = 0; mi < 4; mi++) {
            const int row = m0 + wm + (mi << 4) + er;
            const float v0 = acc[mi][ni][0] + b0, v1 = acc[mi][ni][1] + b1;
            const float v2 = acc[mi][ni][2] + b0, v3 = acc[mi][ni][3] + b1;
            if (OUTMODE == 0) {
                *(float2*)(C + (size_t)row * ND + col)       = make_float2(v0, v1);
                *(float2*)(C + (size_t)(row + 8) * ND + col) = make_float2(v2, v3);
            } else {
                uint32_t h0 = pk2(v0, v1);
                uint32_t l0 = pk2(v0 - bfl(h0), v1 - bfh(h0));
                uint32_t h1 = pk2(v2, v3);
                uint32_t l1 = pk2(v2 - bfl(h1), v3 - bfh(h1));
                *(uint32_t*)(Chi + (size_t)row * ND + col)       = h0;
                *(uint32_t*)(Clo + (size_t)row * ND + col)       = l0;
                *(uint32_t*)(Chi + (size_t)(row + 8) * ND + col) = h1;
                *(uint32_t*)(Clo + (size_t)(row + 8) * ND + col) = l1;
            }
        }
    }
}

// ---------------------------------------------------------------------------
// Tensor-core flash attention, 2-stage cp.async K/V pipeline.
// Grid: (qtile=16, hb=64).  8 warps; warp = 16 query rows; K tile = 64 keys.
// ---------------------------------------------------------------------------
#define APAD 72
#define A_TILE (64*APAD)          // elems per matrix per stage
#define A_STG  (4*A_TILE)

__global__ __launch_bounds__(256) void attn_mma(
    const bf16* __restrict__ Qhi, const bf16* __restrict__ Qlo,
    const bf16* __restrict__ Khi, const bf16* __restrict__ Klo,
    const bf16* __restrict__ Vhi, const bf16* __restrict__ Vlo,
    bf16* __restrict__ Ohi, bf16* __restrict__ Olo)
{
    extern __shared__ bf16 sm[];
    bf16* sQh = sm;                   // 128 x APAD
    bf16* sQl = sQh + 128*APAD;
    bf16* sKV = sQl + 128*APAD;       // 2 stages x (Kh,Kl,Vh,Vl) 64 x APAD

    const int tid = threadIdx.x;
    const int lane = tid & 31, wid = tid >> 5;
    const int hb = blockIdx.y;
    const int b  = hb & 3, h = hb >> 2;
    const int q0 = blockIdx.x << 7;
    const size_t base = (size_t)b * SEQ * ND + h * HD;

    const uint32_t sKVB = smem_u32(sKV);

    // load-thread mapping for K/V (64 rows x 8 chunks): 2 iters of 256 threads
    const int kr0 = tid >> 3, kc = (tid & 7) << 3;     // rows 0..31
    const uint32_t kso0 = (uint32_t)(kr0*APAD + kc) * 2;
    const uint32_t kso1 = (uint32_t)((kr0+32)*APAD + kc) * 2;

    auto load_kv = [&](int stage, int k0) {
        const uint32_t sb = sKVB + (uint32_t)stage * A_STG * 2;
        const size_t g0 = base + (size_t)(k0 + kr0) * ND + kc;
        const size_t g1 = base + (size_t)(k0 + kr0 + 32) * ND + kc;
        cp16(sb + 0*A_TILE*2 + kso0, Khi + g0);
        cp16(sb + 0*A_TILE*2 + kso1, Khi + g1);
        cp16(sb + 1*A_TILE*2 + kso0, Klo + g0);
        cp16(sb + 1*A_TILE*2 + kso1, Klo + g1);
        cp16(sb + 2*A_TILE*2 + kso0, Vhi + g0);
        cp16(sb + 2*A_TILE*2 + kso1, Vhi + g1);
        cp16(sb + 3*A_TILE*2 + kso0, Vlo + g0);
        cp16(sb + 3*A_TILE*2 + kso1, Vlo + g1);
        cp_commit();
    };

    // --- load Q tile (128 x 64 hi/lo) ---
    for (int i = tid; i < 128*8; i += 256) {
        const int r = i >> 3, c8 = (i & 7) << 3;
        const size_t g = base + (size_t)(q0 + r) * ND + c8;
        *(int4*)&sQh[r*APAD + c8] = *(const int4*)(Qhi + g);
        *(int4*)&sQl[r*APAD + c8] = *(const int4*)(Qlo + g);
    }
    load_kv(0, 0);
    __syncthreads();

    // --- Q fragments (hoisted) ---
    const int a_row  = lane & 15;
    const int a_koff = (lane >> 4) << 3;
    uint32_t qh[4][4], ql[4][4];
    #pragma unroll
    for (int ks = 0; ks < 4; ks++) {
        const uint32_t off =
            (uint32_t)(((wid*16 + a_row)*APAD + ks*16 + a_koff) * 2);
        ldsm4(qh[ks], smem_u32(sQh) + off);
        ldsm4(ql[ks], smem_u32(sQl) + off);
    }

    const int b_row  = ((lane >> 4) << 3) + (lane & 7);
    const int b_koff = ((lane >> 3) & 1) << 3;
    const int v_krow = (((lane >> 3) & 1) << 3) + (lane & 7);
    const int v_doff = (lane >> 4) << 3;

    float m0v = -1e30f, m1v = -1e30f, l0v = 0.f, l1v = 0.f;
    float o[8][4] = {};

    for (int kt = 0; kt < 32; kt++) {
        if (kt + 1 < 32) { load_kv((kt + 1) & 1, (kt + 1) << 6); cp_wait<1>(); }
        else             { cp_wait<0>(); }
        __syncthreads();

        const uint32_t sb = sKVB + (uint32_t)(kt & 1) * A_STG * 2;
        const uint32_t sKhB = sb, sKlB = sb + A_TILE*2;
        const uint32_t sVhB = sb + 2*A_TILE*2, sVlB = sb + 3*A_TILE*2;

        // --- S = Q K^T  (16 x 64 per warp) ---
        float s[8][4] = {};
        #pragma unroll
        for (int ks = 0; ks < 4; ks++) {
            #pragma unroll
            for (int ng = 0; ng < 4; ng++) {
                const uint32_t off =
                    (uint32_t)(((ng*16 + b_row)*APAD + ks*16 + b_koff) * 2);
                uint32_t kbh[4], kbl[4];
                ldsm4(kbh, sKhB + off);
                ldsm4(kbl, sKlB + off);
                mma_bf16(s[ng*2],   qh[ks], kbh);
                mma_bf16(s[ng*2+1], qh[ks], kbh + 2);
                mma_bf16(s[ng*2],   qh[ks], kbl);
                mma_bf16(s[ng*2+1], qh[ks], kbl + 2);
                mma_bf16(s[ng*2],   ql[ks], kbh);
                mma_bf16(s[ng*2+1], ql[ks], kbh + 2);
            }
        }

        // --- online softmax ---
        float mx0 = m0v, mx1 = m1v;
        #pragma unroll
        for (int f = 0; f < 8; f++) {
            mx0 = fmaxf(mx0, fmaxf(s[f][0], s[f][1]));
            mx1 = fmaxf(mx1, fmaxf(s[f][2], s[f][3]));
        }
        mx0 = fmaxf(mx0, __shfl_xor_sync(0xffffffffu, mx0, 1));
        mx0 = fmaxf(mx0, __shfl_xor_sync(0xffffffffu, mx0, 2));
        mx1 = fmaxf(mx1, __shfl_xor_sync(0xffffffffu, mx1, 1));
        mx1 = fmaxf(mx1, __shfl_xor_sync(0xffffffffu, mx1, 2));
        const float sc0 = __expf(m0v - mx0);
        const float sc1 = __expf(m1v - mx1);
        float sum0 = 0.f, sum1 = 0.f;
        #pragma unroll
        for (int f = 0; f < 8; f++) {
            s[f][0] = __expf(s[f][0] - mx0);
            s[f][1] = __expf(s[f][1] - mx0);
            s[f][2] = __expf(s[f][2] - mx1);
            s[f][3] = __expf(s[f][3] - mx1);
            sum0 += s[f][0] + s[f][1];
            sum1 += s[f][2] + s[f][3];
        }
        sum0 += __shfl_xor_sync(0xffffffffu, sum0, 1);
        sum0 += __shfl_xor_sync(0xffffffffu, sum0, 2);
        sum1 += __shfl_xor_sync(0xffffffffu, sum1, 1);
        sum1 += __shfl_xor_sync(0xffffffffu, sum1, 2);
        l0v = l0v * sc0 + sum0;  m0v = mx0;
        l1v = l1v * sc1 + sum1;  m1v = mx1;
        #pragma unroll
        for (int f = 0; f < 8; f++) {
            o[f][0] *= sc0; o[f][1] *= sc0;
            o[f][2] *= sc1; o[f][3] *= sc1;
        }

        // --- pack P -> bf16 hi/lo A-fragments ---
        uint32_t ph[4][4], pl[4][4];
        #pragma unroll
        for (int ksp = 0; ksp < 4; ksp++) {
            const float* e = s[2*ksp];
            const float* oq = s[2*ksp+1];
            ph[ksp][0] = pk2(e[0], e[1]);
            pl[ksp][0] = pk2(e[0] - bfl(ph[ksp][0]), e[1] - bfh(ph[ksp][0]));
            ph[ksp][1] = pk2(e[2], e[3]);
            pl[ksp][1] = pk2(e[2] - bfl(ph[ksp][1]), e[3] - bfh(ph[ksp][1]));
            ph[ksp][2] = pk2(oq[0], oq[1]);
            pl[ksp][2] = pk2(oq[0] - bfl(ph[ksp][2]), oq[1] - bfh(ph[ksp][2]));
            ph[ksp][3] = pk2(oq[2], oq[3]);
            pl[ksp][3] = pk2(oq[2] - bfl(ph[ksp][3]), oq[3] - bfh(ph[ksp][3]));
        }

        // --- O += P V ---
        #pragma unroll
        for (int ksp = 0; ksp < 4; ksp++) {
            #pragma unroll
            for (int dg = 0; dg < 4; dg++) {
                const uint32_t off =
                    (uint32_t)(((ksp*16 + v_krow)*APAD + dg*16 + v_doff) * 2);
                uint32_t vbh[4], vbl[4];
                ldsm4t(vbh, sVhB + off);
                ldsm4t(vbl, sVlB + off);
                mma_bf16(o[dg*2],   ph[ksp], vbh);
                mma_bf16(o[dg*2+1], ph[ksp], vbh + 2);
                mma_bf16(o[dg*2],   ph[ksp], vbl);
                mma_bf16(o[dg*2+1], ph[ksp], vbl + 2);
                mma_bf16(o[dg*2],   pl[ksp], vbh);
                mma_bf16(o[dg*2+1], pl[ksp], vbh + 2);
            }
        }
        __syncthreads();
    }

    // --- normalize + write hi/lo bf16 output ---
    const float inv0 = 1.0f / l0v, inv1 = 1.0f / l1v;
    const int r0 = q0 + wid*16 + (lane >> 2);
    const int ec = (lane & 3) << 1;
    #pragma unroll
    for (int dg = 0; dg < 8; dg++) {
        const int col = dg*8 + ec;
        const size_t g0 = base + (size_t)r0 * ND + col;
        const size_t g1 = base + (size_t)(r0 + 8) * ND + col;
        const float v0 = o[dg][0]*inv0, v1 = o[dg][1]*inv0;
        const float v2 = o[dg][2]*inv1, v3 = o[dg][3]*inv1;
        uint32_t h0 = pk2(v0, v1);
        uint32_t l0 = pk2(v0 - bfl(h0), v1 - bfh(h0));
        uint32_t h1 = pk2(v2, v3);
        uint32_t l1 = pk2(v2 - bfl(h1), v3 - bfh(h1));
        *(uint32_t*)(Ohi + g0) = h0;
        *(uint32_t*)(Olo + g0) = l0;
        *(uint32_t*)(Ohi + g1) = h1;
        *(uint32_t*)(Olo + g1) = l1;
    }
}

// ---------------------------------------------------------------------------
extern "C" void kernel_launch(void* const* d_in, const int* in_sizes, int n_in,
                              void* d_out, int out_size)
{
    const float* x  = (const float*)d_in[0];
    const float* Wq = (const float*)d_in[1];
    const float* bq = (const float*)d_in[2];
    const float* Wk = (const float*)d_in[3];
    const float* bk = (const float*)d_in[4];
    const float* Wv = (const float*)d_in[5];
    const float* bv = (const float*)d_in[6];
    const float* Wp = (const float*)d_in[7];
    const float* bp = (const float*)d_in[8];
    float* out = (float*)d_out;

    bf16 *xhi, *xlo, *whi, *wlo;
    bf16 *qhi, *qlo, *khi, *klo, *vhi, *vlo, *ohi, *olo;
    cudaGetSymbolAddress((void**)&xhi, g_xhi);
    cudaGetSymbolAddress((void**)&xlo, g_xlo);
    cudaGetSymbolAddress((void**)&whi, g_whi);
    cudaGetSymbolAddress((void**)&wlo, g_wlo);
    cudaGetSymbolAddress((void**)&qhi, g_qhi);
    cudaGetSymbolAddress((void**)&qlo, g_qlo);
    cudaGetSymbolAddress((void**)&khi, g_khi);
    cudaGetSymbolAddress((void**)&klo, g_klo);
    cudaGetSymbolAddress((void**)&vhi, g_vhi);
    cudaGetSymbolAddress((void**)&vlo, g_vlo);
    cudaGetSymbolAddress((void**)&ohi, g_ohi);
    cudaGetSymbolAddress((void**)&olo, g_olo);

    const size_t WSZ = (size_t)ND * ND;

    split_f32<<<(MTOT*ND/4 + 255)/256, 256>>>(x,  xhi, xlo, MTOT*ND/4);
    split_f32<<<(ND*ND/4 + 255)/256, 256>>>(Wq, whi + 0*WSZ, wlo + 0*WSZ, ND*ND/4);
    split_f32<<<(ND*ND/4 + 255)/256, 256>>>(Wk, whi + 1*WSZ, wlo + 1*WSZ, ND*ND/4);
    split_f32<<<(ND*ND/4 + 255)/256, 256>>>(Wv, whi + 2*WSZ, wlo + 2*WSZ, ND*ND/4);
    split_f32<<<(ND*ND/4 + 255)/256, 256>>>(Wp, whi + 3*WSZ, wlo + 3*WSZ, ND*ND/4);

    const int gemm_smem = 2 * G_STG * (int)sizeof(bf16);   // 81,920 B
    cudaFuncSetAttribute(gemm_bf16<0>, cudaFuncAttributeMaxDynamicSharedMemorySize,
                         gemm_smem);
    cudaFuncSetAttribute(gemm_bf16<1>, cudaFuncAttributeMaxDynamicSharedMemorySize,
                         gemm_smem);
    const dim3 gg(ND/128, MTOT/128);   // (8, 64)
    gemm_bf16<1><<<gg, 256, gemm_smem>>>(xhi, xlo, whi + 0*WSZ, wlo + 0*WSZ, bq,
                                         nullptr, qhi, qlo);
    gemm_bf16<1><<<gg, 256, gemm_smem>>>(xhi, xlo, whi + 1*WSZ, wlo + 1*WSZ, bk,
                                         nullptr, khi, klo);
    gemm_bf16<1><<<gg, 256, gemm_smem>>>(xhi, xlo, whi + 2*WSZ, wlo + 2*WSZ, bv,
                                         nullptr, vhi, vlo);

    const int attn_smem = (2*128*APAD + 2*A_STG) * (int)sizeof(bf16);  // 110,592 B
    cudaFuncSetAttribute(attn_mma,
                         cudaFuncAttributeMaxDynamicSharedMemorySize, attn_smem);
    attn_mma<<<dim3(SEQ/128, NH*BATCH), 256, attn_smem>>>(
        qhi, qlo, khi, klo, vhi, vlo, ohi, olo);

    gemm_bf16<0><<<gg, 256, gemm_smem>>>(ohi, olo, whi + 3*WSZ, wlo + 3*WSZ, bp,
                                         out, nullptr, nullptr);
}